// round 2
// baseline (speedup 1.0000x reference)
#include <cuda_runtime.h>

// Problem constants (from reference: B=1024, S=200, Q=512)
#define PB 1024
#define PS 200
#define PQ 512
#define ROWS (PB * (PS - 1))          // 203,776 (b, s+1) rows
#define WARPS_PER_BLOCK 16
#define THREADS (WARPS_PER_BLOCK * 32)
#define NCHUNK 16                     // 16 chunks x 64 elements (256B) per 4KB row

__global__ void init_out_kernel(float* out) {
    if (threadIdx.x == 0) out[0] = 0.0f;
}

// One warp per (b, s1) row with s1 in [1, S).
// Scans batch[b, s1, 0:2Q] (4 KB) in sixteen 256B chunks (one float2 per lane)
// with early exit once the single one-hot nonzero is found. Then gathers
// pred[b, s1-1, qid] and accumulates the log-likelihood term.
__global__ __launch_bounds__(THREADS)
void loss_kernel(const float* __restrict__ pred,
                 const float* __restrict__ batch,
                 float* __restrict__ out)
{
    __shared__ float warpsum[WARPS_PER_BLOCK];

    const int lane   = threadIdx.x & 31;
    const int wlocal = threadIdx.x >> 5;
    const int row    = blockIdx.x * WARPS_PER_BLOCK + wlocal;

    float contrib = 0.0f;

    if (row < ROWS) {
        const int b  = row / (PS - 1);
        const int s1 = row - b * (PS - 1) + 1;      // 1..S-1

        // batch row base: [b, s1, 0], row length 2Q = 1024 floats = 4 KB
        const float2* __restrict__ brow =
            reinterpret_cast<const float2*>(batch + ((size_t)b * PS + s1) * (2 * PQ));

        int idx = -1;   // element index of the nonzero within [0, 2Q)

        // 16 chunks x 256B. Each lane loads one float2 (8 contiguous bytes).
        #pragma unroll
        for (int c = 0; c < NCHUNK; c++) {
            const int v2 = c * 32 + lane;           // float2 index within row
            float2 v = __ldg(brow + v2);
            const int e = v2 * 2;                   // element index
            if (v.x != 0.0f) idx = e + 0;
            if (v.y != 0.0f) idx = e + 1;
            // Early exit: skip remaining chunks once any lane found it.
            if (__ballot_sync(0xffffffffu, idx >= 0)) break;
        }

        // Warp max-reduce the found index to lane 0.
        #pragma unroll
        for (int off = 16; off > 0; off >>= 1)
            idx = max(idx, __shfl_xor_sync(0xffffffffu, idx, off));

        if (lane == 0 && idx >= 0) {
            const int correct = (idx < PQ) ? 1 : 0;
            const int qid     = correct ? idx : (idx - PQ);
            // p = pred[b, s1-1, qid]
            const float p = __ldg(pred + ((size_t)b * PS + (s1 - 1)) * PQ + qid);
            // a = correct; ll = a*log(p) + (1-a)*log(1-p)
            contrib = correct ? logf(p) : logf(1.0f - p);
        }
    }

    if (lane == 0) warpsum[wlocal] = contrib;
    __syncthreads();

    if (threadIdx.x == 0) {
        float s = 0.0f;
        #pragma unroll
        for (int i = 0; i < WARPS_PER_BLOCK; i++) s += warpsum[i];
        atomicAdd(out, -s);   // loss = -sum(ll)
    }
}

extern "C" void kernel_launch(void* const* d_in, const int* in_sizes, int n_in,
                              void* d_out, int out_size)
{
    const float* pred  = (const float*)d_in[0];   // [B, S, Q] fp32
    const float* batch = (const float*)d_in[1];   // [B, S, 2Q] fp32
    float* out = (float*)d_out;                   // [1] fp32

    init_out_kernel<<<1, 32>>>(out);

    const int blocks = (ROWS + WARPS_PER_BLOCK - 1) / WARPS_PER_BLOCK;
    loss_kernel<<<blocks, THREADS>>>(pred, batch, out);
}

// round 3
// speedup vs baseline: 2.1477x; 2.1477x over previous
#include <cuda_runtime.h>

// Problem constants (from reference: B=1024, S=200, Q=512)
#define PB 1024
#define PS 200
#define PQ 512
#define ROWS (PB * (PS - 1))          // 203,776 (b, s+1) rows
#define WARPS_PER_BLOCK 16
#define THREADS (WARPS_PER_BLOCK * 32)
#define RPW 4                         // rows processed concurrently per warp
#define NCHUNK 4                      // 4 chunks x 1KB per 4KB row

__global__ void init_out_kernel(float* out) {
    if (threadIdx.x == 0) out[0] = 0.0f;
}

// Each warp owns RPW consecutive (b, s1) rows and scans them CONCURRENTLY:
// per round it issues the next 1KB chunk load for every still-unfinished row
// (independent loads -> high MLP), then tests + ballots each. A row stops
// loading as soon as its one-hot nonzero is found (early exit preserves the
// ~0.575 expected byte fraction), while interleaving slashes the number of
// serial load->ballot round trips per warp.
__global__ __launch_bounds__(THREADS)
void loss_kernel(const float* __restrict__ pred,
                 const float* __restrict__ batch,
                 float* __restrict__ out)
{
    __shared__ float warpsum[WARPS_PER_BLOCK];

    const int lane   = threadIdx.x & 31;
    const int wlocal = threadIdx.x >> 5;
    const int wglob  = blockIdx.x * WARPS_PER_BLOCK + wlocal;
    const int rowBase = wglob * RPW;

    const float4* __restrict__ brow[RPW];
    int  idx[RPW];
    bool done[RPW];   // warp-uniform (set from ballot)

    #pragma unroll
    for (int r = 0; r < RPW; r++) {
        const int row = rowBase + r;
        idx[r] = -1;
        if (row < ROWS) {
            const int b  = row / (PS - 1);
            const int s1 = row - b * (PS - 1) + 1;   // 1..S-1
            brow[r] = reinterpret_cast<const float4*>(
                batch + ((size_t)b * PS + s1) * (2 * PQ));
            done[r] = false;
        } else {
            brow[r] = nullptr;
            done[r] = true;
        }
    }

    #pragma unroll
    for (int c = 0; c < NCHUNK; c++) {
        // Issue phase: batch all loads for unfinished rows (independent).
        float4 va[RPW], vb[RPW];
        #pragma unroll
        for (int r = 0; r < RPW; r++) {
            if (!done[r]) {
                const int v4 = c * 64 + lane * 2;    // float4 index within row
                va[r] = __ldg(brow[r] + v4 + 0);
                vb[r] = __ldg(brow[r] + v4 + 1);
            }
        }
        // Test phase: locate nonzero, ballot per row.
        bool alldone = true;
        #pragma unroll
        for (int r = 0; r < RPW; r++) {
            if (!done[r]) {
                const int e = (c * 64 + lane * 2) * 4;
                if (va[r].x != 0.0f) idx[r] = e + 0;
                if (va[r].y != 0.0f) idx[r] = e + 1;
                if (va[r].z != 0.0f) idx[r] = e + 2;
                if (va[r].w != 0.0f) idx[r] = e + 3;
                if (vb[r].x != 0.0f) idx[r] = e + 4;
                if (vb[r].y != 0.0f) idx[r] = e + 5;
                if (vb[r].z != 0.0f) idx[r] = e + 6;
                if (vb[r].w != 0.0f) idx[r] = e + 7;
                done[r] = (__ballot_sync(0xffffffffu, idx[r] >= 0) != 0u);
            }
            alldone &= done[r];
        }
        if (alldone) break;
    }

    // Reduce each row's found index to all lanes (max; missing lanes hold -1).
    #pragma unroll
    for (int r = 0; r < RPW; r++) {
        #pragma unroll
        for (int off = 16; off > 0; off >>= 1)
            idx[r] = max(idx[r], __shfl_xor_sync(0xffffffffu, idx[r], off));
    }

    // Lane r (r < RPW) performs row r's gather + log so the RPW scattered
    // pred loads and logf evaluations run in parallel across lanes.
    float contrib = 0.0f;
    if (lane < RPW) {
        const int row = rowBase + lane;
        const int id  = idx[lane];
        if (row < ROWS && id >= 0) {
            const int b  = row / (PS - 1);
            const int s1 = row - b * (PS - 1) + 1;
            const int correct = (id < PQ) ? 1 : 0;
            const int qid     = correct ? id : (id - PQ);
            const float p = __ldg(pred + ((size_t)b * PS + (s1 - 1)) * PQ + qid);
            contrib = correct ? logf(p) : logf(1.0f - p);
        }
    }

    // Warp-sum the per-lane contributions.
    #pragma unroll
    for (int off = 16; off > 0; off >>= 1)
        contrib += __shfl_xor_sync(0xffffffffu, contrib, off);

    if (lane == 0) warpsum[wlocal] = contrib;
    __syncthreads();

    if (threadIdx.x == 0) {
        float s = 0.0f;
        #pragma unroll
        for (int i = 0; i < WARPS_PER_BLOCK; i++) s += warpsum[i];
        atomicAdd(out, -s);   // loss = -sum(ll)
    }
}

extern "C" void kernel_launch(void* const* d_in, const int* in_sizes, int n_in,
                              void* d_out, int out_size)
{
    const float* pred  = (const float*)d_in[0];   // [B, S, Q] fp32
    const float* batch = (const float*)d_in[1];   // [B, S, 2Q] fp32
    float* out = (float*)d_out;                   // [1] fp32

    init_out_kernel<<<1, 32>>>(out);

    const int rows_per_block = WARPS_PER_BLOCK * RPW;
    const int blocks = (ROWS + rows_per_block - 1) / rows_per_block;
    loss_kernel<<<blocks, THREADS>>>(pred, batch, out);
}

// round 4
// speedup vs baseline: 2.1973x; 1.0231x over previous
#include <cuda_runtime.h>

// Problem constants (from reference: B=1024, S=200, Q=512)
#define PB 1024
#define PS 200
#define PQ 512
#define ROWS (PB * (PS - 1))          // 203,776 (b, s+1) rows
#define WARPS_PER_BLOCK 8
#define THREADS (WARPS_PER_BLOCK * 32)
#define RPW 8                         // rows processed concurrently per warp
#define NCHUNK 8                      // 8 chunks x 512B per 4KB row

__global__ void init_out_kernel(float* out) {
    if (threadIdx.x == 0) out[0] = 0.0f;
}

// Each warp owns RPW consecutive (b, s1) rows and scans them CONCURRENTLY in
// 512B chunks (one float4 per lane per row per round). Per round the warp
// issues the next chunk load for every still-unfinished row (8 independent
// loads -> 4KB in flight per warp), then tests + ballots each row. A row
// stops loading as soon as its one-hot nonzero is found: expected read
// fraction = 0.5125 of each 4KB row, while the 8-way interleave keeps the
// serial load->ballot dependency chain down to ~0.9 rounds per row.
__global__ __launch_bounds__(THREADS)
void loss_kernel(const float* __restrict__ pred,
                 const float* __restrict__ batch,
                 float* __restrict__ out)
{
    __shared__ float warpsum[WARPS_PER_BLOCK];

    const int lane   = threadIdx.x & 31;
    const int wlocal = threadIdx.x >> 5;
    const int wglob  = blockIdx.x * WARPS_PER_BLOCK + wlocal;
    const int rowBase = wglob * RPW;

    const float4* __restrict__ brow[RPW];
    int  idx[RPW];
    bool done[RPW];   // warp-uniform (set from ballot)

    #pragma unroll
    for (int r = 0; r < RPW; r++) {
        const int row = rowBase + r;
        idx[r] = -1;
        if (row < ROWS) {
            const int b  = row / (PS - 1);
            const int s1 = row - b * (PS - 1) + 1;   // 1..S-1
            brow[r] = reinterpret_cast<const float4*>(
                batch + ((size_t)b * PS + s1) * (2 * PQ));
            done[r] = false;
        } else {
            brow[r] = nullptr;
            done[r] = true;
        }
    }

    #pragma unroll
    for (int c = 0; c < NCHUNK; c++) {
        // Issue phase: batch all loads for unfinished rows (independent).
        float4 v[RPW];
        #pragma unroll
        for (int r = 0; r < RPW; r++) {
            if (!done[r]) {
                v[r] = __ldg(brow[r] + c * 32 + lane);   // float4 index in row
            }
        }
        // Test phase: locate nonzero, ballot per row.
        bool alldone = true;
        #pragma unroll
        for (int r = 0; r < RPW; r++) {
            if (!done[r]) {
                const int e = (c * 32 + lane) * 4;       // element index
                if (v[r].x != 0.0f) idx[r] = e + 0;
                if (v[r].y != 0.0f) idx[r] = e + 1;
                if (v[r].z != 0.0f) idx[r] = e + 2;
                if (v[r].w != 0.0f) idx[r] = e + 3;
                done[r] = (__ballot_sync(0xffffffffu, idx[r] >= 0) != 0u);
            }
            alldone &= done[r];
        }
        if (alldone) break;
    }

    // Reduce each row's found index to all lanes (max; other lanes hold -1).
    #pragma unroll
    for (int r = 0; r < RPW; r++) {
        #pragma unroll
        for (int off = 16; off > 0; off >>= 1)
            idx[r] = max(idx[r], __shfl_xor_sync(0xffffffffu, idx[r], off));
    }

    // Lane r (r < RPW) performs row r's gather + log so the RPW scattered
    // pred loads and logf evaluations run in parallel across lanes.
    float contrib = 0.0f;
    int myidx = -1;
    #pragma unroll
    for (int r = 0; r < RPW; r++)
        if (lane == r) myidx = idx[r];

    if (lane < RPW) {
        const int row = rowBase + lane;
        if (row < ROWS && myidx >= 0) {
            const int b  = row / (PS - 1);
            const int s1 = row - b * (PS - 1) + 1;
            const int correct = (myidx < PQ) ? 1 : 0;
            const int qid     = correct ? myidx : (myidx - PQ);
            const float p = __ldg(pred + ((size_t)b * PS + (s1 - 1)) * PQ + qid);
            contrib = correct ? logf(p) : logf(1.0f - p);
        }
    }

    // Warp-sum the per-lane contributions.
    #pragma unroll
    for (int off = 16; off > 0; off >>= 1)
        contrib += __shfl_xor_sync(0xffffffffu, contrib, off);

    if (lane == 0) warpsum[wlocal] = contrib;
    __syncthreads();

    if (threadIdx.x == 0) {
        float s = 0.0f;
        #pragma unroll
        for (int i = 0; i < WARPS_PER_BLOCK; i++) s += warpsum[i];
        atomicAdd(out, -s);   // loss = -sum(ll)
    }
}

extern "C" void kernel_launch(void* const* d_in, const int* in_sizes, int n_in,
                              void* d_out, int out_size)
{
    const float* pred  = (const float*)d_in[0];   // [B, S, Q] fp32
    const float* batch = (const float*)d_in[1];   // [B, S, 2Q] fp32
    float* out = (float*)d_out;                   // [1] fp32

    init_out_kernel<<<1, 32>>>(out);

    const int rows_per_block = WARPS_PER_BLOCK * RPW;
    const int blocks = (ROWS + rows_per_block - 1) / rows_per_block;
    loss_kernel<<<blocks, THREADS>>>(pred, batch, out);
}

// round 5
// speedup vs baseline: 2.4339x; 1.1077x over previous
#include <cuda_runtime.h>

// Problem constants (from reference: B=1024, S=200, Q=512)
#define PB 1024
#define PS 200
#define PQ 512
#define ROWS (PB * (PS - 1))          // 203,776 = 64 * 3184 (exact grid)
#define WARPS_PER_BLOCK 8
#define THREADS (WARPS_PER_BLOCK * 32)
#define RPW 8                         // rows processed concurrently per warp
#define NCHUNK 8                      // 8 chunks x 512B per 4KB row

__global__ void init_out_kernel(float* out) {
    if (threadIdx.x == 0) out[0] = 0.0f;
}

// Each warp owns 8 consecutive (b, s1) rows, scanned concurrently in 512B
// chunks (one float4 per lane per row per round) with early exit per row.
// The one-hot index is accumulated ARITHMETICALLY (values are exactly 0/1):
//   acc[r] += v.x*(e+1) + v.y*(e+2) + v.z*(e+3) + v.w*(e+4)
// so "found" = (partial != 0) and idx = warp_sum(acc) - 1. Per round the warp
// does ONE __reduce_or_sync over a packed 8-bit found mask instead of 8
// ballots, keeping the load-issue duty cycle high.
__global__ __launch_bounds__(THREADS)
void loss_kernel(const float* __restrict__ pred,
                 const float* __restrict__ batch,
                 float* __restrict__ out)
{
    __shared__ float warpsum[WARPS_PER_BLOCK];

    const int lane   = threadIdx.x & 31;
    const int wlocal = threadIdx.x >> 5;
    const int wglob  = blockIdx.x * WARPS_PER_BLOCK + wlocal;
    const int rowBase = wglob * RPW;   // grid is exact: rowBase+7 < ROWS always

    const float4* __restrict__ batch4 = reinterpret_cast<const float4*>(batch);

    unsigned off4[RPW];   // float4 offset of each row's batch base
    float    acc[RPW];    // arithmetic one-hot index accumulator (idx+1)

    #pragma unroll
    for (int r = 0; r < RPW; r++) {
        const int row = rowBase + r;
        const int b   = row / (PS - 1);
        const int s1  = row - b * (PS - 1) + 1;            // 1..S-1
        off4[r] = (unsigned)(b * PS + s1) * (2 * PQ / 4);  // *256
        acc[r]  = 0.0f;
    }

    unsigned donemask = 0;

    #pragma unroll
    for (int c = 0; c < NCHUNK; c++) {
        // Issue phase: batch all loads for unfinished rows (independent).
        float4 v[RPW];
        #pragma unroll
        for (int r = 0; r < RPW; r++)
            if (!((donemask >> r) & 1u))
                v[r] = __ldg(batch4 + off4[r] + c * 32 + lane);

        // Test phase: pure FMA accumulation + packed found mask.
        unsigned newmask = 0;
        #pragma unroll
        for (int r = 0; r < RPW; r++) {
            if (!((donemask >> r) & 1u)) {
                const float e = (float)((c * 32 + lane) * 4 + 1);
                float s = v[r].x * e;
                s = fmaf(v[r].y, e + 1.0f, s);
                s = fmaf(v[r].z, e + 2.0f, s);
                s = fmaf(v[r].w, e + 3.0f, s);
                acc[r] += s;
                if (s != 0.0f) newmask |= (1u << r);
            }
        }
        // Single warp-wide OR-reduce replaces 8 ballots.
        donemask |= __reduce_or_sync(0xffffffffu, newmask);
        if (donemask == 0xffu) break;
    }

    // Per-row index: warp-sum of acc (exact in fp32, value <= 1024).
    // Lane r keeps row r's result so the 8 gathers + logf run in parallel.
    int myidx = -1;
    #pragma unroll
    for (int r = 0; r < RPW; r++) {
        const int t = __reduce_add_sync(0xffffffffu, (int)acc[r]);  // idx+1
        if (lane == r) myidx = t - 1;
    }

    float contrib = 0.0f;
    if (lane < RPW && myidx >= 0) {
        const int row = rowBase + lane;
        const int b   = row / (PS - 1);
        const int s1  = row - b * (PS - 1) + 1;
        const int correct = (myidx < PQ) ? 1 : 0;
        const int qid     = correct ? myidx : (myidx - PQ);
        const float p = __ldg(pred + ((size_t)b * PS + (s1 - 1)) * PQ + qid);
        contrib = correct ? logf(p) : logf(1.0f - p);
    }

    // Warp-sum the per-lane contributions.
    #pragma unroll
    for (int off = 16; off > 0; off >>= 1)
        contrib += __shfl_xor_sync(0xffffffffu, contrib, off);

    if (lane == 0) warpsum[wlocal] = contrib;
    __syncthreads();

    if (threadIdx.x == 0) {
        float s = 0.0f;
        #pragma unroll
        for (int i = 0; i < WARPS_PER_BLOCK; i++) s += warpsum[i];
        atomicAdd(out, -s);   // loss = -sum(ll)
    }
}

extern "C" void kernel_launch(void* const* d_in, const int* in_sizes, int n_in,
                              void* d_out, int out_size)
{
    const float* pred  = (const float*)d_in[0];   // [B, S, Q] fp32
    const float* batch = (const float*)d_in[1];   // [B, S, 2Q] fp32
    float* out = (float*)d_out;                   // [1] fp32

    init_out_kernel<<<1, 32>>>(out);

    const int rows_per_block = WARPS_PER_BLOCK * RPW;   // 64
    const int blocks = ROWS / rows_per_block;           // 3184 (exact)
    loss_kernel<<<blocks, THREADS>>>(pred, batch, out);
}